// round 3
// baseline (speedup 1.0000x reference)
#include <cuda_runtime.h>
#include <math.h>

// ---------------------------------------------------------------------------
// ENL transformer block (Performer / FAVOR+ linear attention), fp32 baseline.
// B=8, C=256, H=W=64 -> N=4096 tokens/batch, F=256 features, MLP hidden=1024.
// ---------------------------------------------------------------------------

#define TOK   4096
#define BAT   8
#define DIMC  256
#define HID   1024
#define MTOT  (BAT * TOK)          // 32768 rows total

// ------------------------------ scratch ------------------------------------
__device__ float g_t  [(size_t)BAT * TOK * DIMC];   // tokens / residual stream
__device__ float g_h  [(size_t)BAT * TOK * DIMC];   // layernorm output (reused)
__device__ float g_q  [(size_t)BAT * TOK * DIMC];
__device__ float g_k  [(size_t)BAT * TOK * DIMC];
__device__ float g_v  [(size_t)BAT * TOK * DIMC];
__device__ float g_qp [(size_t)BAT * TOK * DIMC];
__device__ float g_kp [(size_t)BAT * TOK * DIMC];
__device__ float g_m  [(size_t)BAT * TOK * HID];    // MLP hidden
__device__ float g_ctx[(size_t)BAT * DIMC * DIMC];  // ctx^T  [b][c][f]
__device__ float g_ksum[BAT * DIMC];
__device__ float g_dq [(size_t)BAT * TOK];          // 0.5*||qn||^2
__device__ float g_dk [(size_t)BAT * TOK];
__device__ float g_di [(size_t)BAT * TOK];          // D_inv

// ---------------------------------------------------------------------------
// K1: transpose [B,C,N] -> [B,N,C], store shortcut t and LayerNorm1 output h.
// Block handles 32 tokens; 256 threads. Coalesced reads via 32x256 smem tile.
// ---------------------------------------------------------------------------
__global__ void __launch_bounds__(256) k_tr_ln(
    const float* __restrict__ x, const float* __restrict__ g,
    const float* __restrict__ bta, float* __restrict__ t, float* __restrict__ h)
{
    __shared__ float tile[32][257];
    int b  = blockIdx.y;
    int n0 = blockIdx.x * 32;
    const float* xb = x + (size_t)b * DIMC * TOK;
    int tx = threadIdx.x & 31, ty = threadIdx.x >> 5;   // ty 0..7
    #pragma unroll 4
    for (int cc = 0; cc < 32; cc++) {
        int c = cc * 8 + ty;
        tile[tx][c] = xb[(size_t)c * TOK + n0 + tx];
    }
    __syncthreads();
    // warp per token: warp ty handles tokens ty, ty+8, ty+16, ty+24
    for (int rep = 0; rep < 4; rep++) {
        int nl = ty + rep * 8;
        float v[8], s = 0.f, sq = 0.f;
        #pragma unroll
        for (int i = 0; i < 8; i++) {
            v[i] = tile[nl][tx + 32 * i];
            s += v[i]; sq += v[i] * v[i];
        }
        #pragma unroll
        for (int o = 16; o; o >>= 1) {
            s  += __shfl_xor_sync(~0u, s,  o);
            sq += __shfl_xor_sync(~0u, sq, o);
        }
        float mu  = s * (1.f / DIMC);
        float var = sq * (1.f / DIMC) - mu * mu;
        float inv = rsqrtf(var + 1e-5f);
        size_t base = ((size_t)b * TOK + n0 + nl) * DIMC;
        #pragma unroll
        for (int i = 0; i < 8; i++) {
            int c = tx + 32 * i;
            t[base + c] = v[i];
            h[base + c] = (v[i] - mu) * inv * g[c] + bta[c];
        }
    }
}

// ---------------------------------------------------------------------------
// LayerNorm2 (no transpose): warp per token.
// ---------------------------------------------------------------------------
__global__ void __launch_bounds__(256) k_ln(
    const float* __restrict__ t, const float* __restrict__ g,
    const float* __restrict__ bta, float* __restrict__ h)
{
    int tok  = blockIdx.x * 8 + (threadIdx.x >> 5);
    int lane = threadIdx.x & 31;
    const float* row = t + (size_t)tok * DIMC;
    float v[8], s = 0.f, sq = 0.f;
    #pragma unroll
    for (int i = 0; i < 8; i++) {
        v[i] = row[lane + 32 * i];
        s += v[i]; sq += v[i] * v[i];
    }
    #pragma unroll
    for (int o = 16; o; o >>= 1) {
        s  += __shfl_xor_sync(~0u, s,  o);
        sq += __shfl_xor_sync(~0u, sq, o);
    }
    float mu  = s * (1.f / DIMC);
    float var = sq * (1.f / DIMC) - mu * mu;
    float inv = rsqrtf(var + 1e-5f);
    float* hr = h + (size_t)tok * DIMC;
    #pragma unroll
    for (int i = 0; i < 8; i++) {
        int c = lane + 32 * i;
        hr[c] = (v[i] - mu) * inv * g[c] + bta[c];
    }
}

// ---------------------------------------------------------------------------
// L2-normalize q,k rows in place (eps=5e-5) + store diag = 0.5*||qn||^2.
// ---------------------------------------------------------------------------
__global__ void __launch_bounds__(256) k_norm(
    float* __restrict__ q, float* __restrict__ k,
    float* __restrict__ dq, float* __restrict__ dk)
{
    int tok  = blockIdx.x * 8 + (threadIdx.x >> 5);
    int lane = threadIdx.x & 31;
    for (int s2 = 0; s2 < 2; s2++) {
        float* row = (s2 == 0 ? q : k) + (size_t)tok * DIMC;
        float v[8], sq = 0.f;
        #pragma unroll
        for (int i = 0; i < 8; i++) {
            v[i] = row[lane + 32 * i];
            sq += v[i] * v[i];
        }
        #pragma unroll
        for (int o = 16; o; o >>= 1) sq += __shfl_xor_sync(~0u, sq, o);
        float nrm = sqrtf(sq);
        float sc  = 1.0f / fmaxf(nrm, 5e-5f);
        #pragma unroll
        for (int i = 0; i < 8; i++) row[lane + 32 * i] = v[i] * sc;
        if (lane == 0) (s2 == 0 ? dq : dk)[tok] = 0.5f * sq * sc * sc;
    }
}

// ---------------------------------------------------------------------------
// Generic fused GEMM: C[M,N] = epilogue( A[M,K] @ W[N,K]^T + bias ).
// 128x128 tile, BK=8, 256 threads, 8x8 microtile split as 2x2 blocks of 4x4
// (frag cols tx*4 and 64+tx*4 -> <=2-way LDS conflicts).
// modes: 0 bias | 1 bias+gelu | 2 bias+res | 3 FAVOR+ featuremap | 4 res+dinv*acc
// wbatch>0: per-batch W (W += (m0/TOK)*wbatch) — used for the ctx GEMM.
// ---------------------------------------------------------------------------
__global__ void __launch_bounds__(256) k_gemm(
    const float* __restrict__ A, const float* __restrict__ W,
    const float* __restrict__ bias, float* __restrict__ Cout,
    int K, int N, int mode,
    const float* __restrict__ aux, const float* __restrict__ res,
    int wbatch)
{
    __shared__ float As[8][129];
    __shared__ float Ws[8][129];
    int m0 = blockIdx.y * 128;
    int n0 = blockIdx.x * 128;
    const float* Wp = W + (wbatch ? (size_t)(m0 / TOK) * wbatch : 0);
    int tid = threadIdx.x;
    int lc = tid & 7, lr = tid >> 3;          // load mapping (8 cols x 32 rows)
    int tx = tid & 15, ty = tid >> 4;          // compute mapping (16 x 16)
    float acc[8][8];
    #pragma unroll
    for (int i = 0; i < 8; i++)
        #pragma unroll
        for (int j = 0; j < 8; j++) acc[i][j] = 0.f;

    for (int k0 = 0; k0 < K; k0 += 8) {
        #pragma unroll
        for (int i = 0; i < 4; i++) {
            int row = lr + 32 * i;
            As[lc][row] = A [(size_t)(m0 + row) * K + k0 + lc];
            Ws[lc][row] = Wp[(size_t)(n0 + row) * K + k0 + lc];
        }
        __syncthreads();
        #pragma unroll
        for (int kk = 0; kk < 8; kk++) {
            float a[8], b[8];
            #pragma unroll
            for (int i = 0; i < 4; i++) {
                a[i]     = As[kk][ty * 4 + i];
                a[i + 4] = As[kk][64 + ty * 4 + i];
                b[i]     = Ws[kk][tx * 4 + i];
                b[i + 4] = Ws[kk][64 + tx * 4 + i];
            }
            #pragma unroll
            for (int i = 0; i < 8; i++)
                #pragma unroll
                for (int j = 0; j < 8; j++)
                    acc[i][j] += a[i] * b[j];
        }
        __syncthreads();
    }

    #pragma unroll
    for (int i = 0; i < 8; i++) {
        int m = m0 + ty * 4 + (i & 3) + (i >> 2) * 64;
        #pragma unroll
        for (int j = 0; j < 8; j++) {
            int n = n0 + tx * 4 + (j & 3) + (j >> 2) * 64;
            float v = acc[i][j];
            if (mode == 0)      { v += bias[n]; }
            else if (mode == 1) { v += bias[n]; v = v * normcdff(v); }
            else if (mode == 2) { v += bias[n]; v += res[(size_t)m * N + n]; }
            else if (mode == 3) { v = 0.0625f * (expf(v - aux[m]) + 1e-4f); }
            else                { v = res[(size_t)m * N + n] + aux[m] * v; }
            Cout[(size_t)m * N + n] = v;
        }
    }
}

// ---------------------------------------------------------------------------
// ctx^T[b][c][f] += sum_n v[b][n][c] * kp[b][n][f]   (A^T B, K=4096, ksplit=8)
// 64x64 tiles, 32-deep K chunks, fp32 atomic accumulate.
// ---------------------------------------------------------------------------
__global__ void __launch_bounds__(256) k_atb(
    const float* __restrict__ V, const float* __restrict__ KP,
    float* __restrict__ CT)
{
    __shared__ float Vs[32][68];
    __shared__ float Ks[32][68];
    int b  = blockIdx.z >> 3;
    int ks = blockIdx.z & 7;
    int c0 = blockIdx.y * 64;
    int f0 = blockIdx.x * 64;
    const float* Vp = V  + (size_t)b * TOK * DIMC;
    const float* Kp = KP + (size_t)b * TOK * DIMC;
    int tid = threadIdx.x;
    int fc = tid & 15, r0 = tid >> 4;
    int tx = tid & 15, ty = tid >> 4;
    float acc[4][4];
    #pragma unroll
    for (int i = 0; i < 4; i++)
        #pragma unroll
        for (int j = 0; j < 4; j++) acc[i][j] = 0.f;

    int nbeg = ks * (TOK / 8);
    for (int nt = 0; nt < TOK / 8; nt += 32) {
        #pragma unroll
        for (int rr = 0; rr < 32; rr += 16) {
            int n = nbeg + nt + r0 + rr;
            float4 a = *(const float4*)&Vp[(size_t)n * DIMC + c0 + fc * 4];
            float4 c = *(const float4*)&Kp[(size_t)n * DIMC + f0 + fc * 4];
            Vs[r0 + rr][fc * 4 + 0] = a.x; Vs[r0 + rr][fc * 4 + 1] = a.y;
            Vs[r0 + rr][fc * 4 + 2] = a.z; Vs[r0 + rr][fc * 4 + 3] = a.w;
            Ks[r0 + rr][fc * 4 + 0] = c.x; Ks[r0 + rr][fc * 4 + 1] = c.y;
            Ks[r0 + rr][fc * 4 + 2] = c.z; Ks[r0 + rr][fc * 4 + 3] = c.w;
        }
        __syncthreads();
        #pragma unroll
        for (int kk = 0; kk < 32; kk++) {
            float a[4], bb[4];
            #pragma unroll
            for (int i = 0; i < 4; i++) { a[i] = Vs[kk][ty * 4 + i]; bb[i] = Ks[kk][tx * 4 + i]; }
            #pragma unroll
            for (int i = 0; i < 4; i++)
                #pragma unroll
                for (int j = 0; j < 4; j++) acc[i][j] += a[i] * bb[j];
        }
        __syncthreads();
    }
    float* Cb = CT + (size_t)b * DIMC * DIMC;
    #pragma unroll
    for (int i = 0; i < 4; i++)
        #pragma unroll
        for (int j = 0; j < 4; j++)
            atomicAdd(&Cb[(size_t)(c0 + ty * 4 + i) * DIMC + f0 + tx * 4 + j], acc[i][j]);
}

// ---------------------------------------------------------------------------
// small helpers
// ---------------------------------------------------------------------------
__global__ void k_zero(float* __restrict__ p, int n)
{
    int i = blockIdx.x * 256 + threadIdx.x;
    if (i < n) p[i] = 0.f;
}

__global__ void __launch_bounds__(256) k_colsum(
    const float* __restrict__ kp, float* __restrict__ ksum)
{
    int b = blockIdx.y, ch = blockIdx.x;
    int f = threadIdx.x;
    const float* base = kp + ((size_t)b * TOK + ch * 128) * DIMC + f;
    float s = 0.f;
    #pragma unroll 8
    for (int i = 0; i < 128; i++) s += base[(size_t)i * DIMC];
    atomicAdd(&ksum[b * DIMC + f], s);
}

__global__ void __launch_bounds__(256) k_dinv(
    const float* __restrict__ qp, const float* __restrict__ ksum,
    float* __restrict__ di)
{
    int tok  = blockIdx.x * 8 + (threadIdx.x >> 5);
    int lane = threadIdx.x & 31;
    int b = tok >> 12;
    const float* row = qp + (size_t)tok * DIMC;
    const float* ks  = ksum + b * DIMC;
    float s = 0.f;
    #pragma unroll
    for (int i = 0; i < 8; i++) { int c = lane + 32 * i; s += row[c] * ks[c]; }
    #pragma unroll
    for (int o = 16; o; o >>= 1) s += __shfl_xor_sync(~0u, s, o);
    if (lane == 0) di[tok] = 1.0f / s;
}

// ---------------------------------------------------------------------------
// output transpose: [B,N,C] -> [B,C,H,W] (=[B,C,N])
// ---------------------------------------------------------------------------
__global__ void __launch_bounds__(256) k_out_tr(
    const float* __restrict__ t, float* __restrict__ out)
{
    __shared__ float tile[32][33];
    int b  = blockIdx.z;
    int n0 = blockIdx.x * 32;
    int c0 = blockIdx.y * 32;
    int tx = threadIdx.x & 31, ty = threadIdx.x >> 5;
    #pragma unroll
    for (int i = 0; i < 32; i += 8)
        tile[ty + i][tx] = t[((size_t)b * TOK + n0 + ty + i) * DIMC + c0 + tx];
    __syncthreads();
    #pragma unroll
    for (int i = 0; i < 32; i += 8)
        out[((size_t)b * DIMC + c0 + ty + i) * TOK + n0 + tx] = tile[tx][ty + i];
}

// ---------------------------------------------------------------------------
// host launch
// ---------------------------------------------------------------------------
extern "C" void kernel_launch(void* const* d_in, const int* in_sizes, int n_in,
                              void* d_out, int out_size)
{
    const float* x    = (const float*)d_in[0];
    const float* proj = (const float*)d_in[1];
    const float* wq   = (const float*)d_in[2];
    const float* bq   = (const float*)d_in[3];
    const float* wk   = (const float*)d_in[4];
    const float* bk   = (const float*)d_in[5];
    const float* wa   = (const float*)d_in[6];
    const float* ba   = (const float*)d_in[7];
    const float* g1   = (const float*)d_in[8];
    const float* b1   = (const float*)d_in[9];
    const float* g2   = (const float*)d_in[10];
    const float* b2   = (const float*)d_in[11];
    const float* w1   = (const float*)d_in[12];
    const float* fb1  = (const float*)d_in[13];
    const float* w2   = (const float*)d_in[14];
    const float* fb2  = (const float*)d_in[15];
    float* out = (float*)d_out;
    (void)in_sizes; (void)n_in; (void)out_size;

    float *t, *h, *q, *k, *v, *qp, *kp, *m, *ctx, *ksum, *dq, *dk, *di;
    cudaGetSymbolAddress((void**)&t,    g_t);
    cudaGetSymbolAddress((void**)&h,    g_h);
    cudaGetSymbolAddress((void**)&q,    g_q);
    cudaGetSymbolAddress((void**)&k,    g_k);
    cudaGetSymbolAddress((void**)&v,    g_v);
    cudaGetSymbolAddress((void**)&qp,   g_qp);
    cudaGetSymbolAddress((void**)&kp,   g_kp);
    cudaGetSymbolAddress((void**)&m,    g_m);
    cudaGetSymbolAddress((void**)&ctx,  g_ctx);
    cudaGetSymbolAddress((void**)&ksum, g_ksum);
    cudaGetSymbolAddress((void**)&dq,   g_dq);
    cudaGetSymbolAddress((void**)&dk,   g_dk);
    cudaGetSymbolAddress((void**)&di,   g_di);

    // 1. transpose + LN1 (t = shortcut, h = normed)
    k_tr_ln<<<dim3(TOK / 32, BAT), 256>>>(x, g1, b1, t, h);

    // 2. q, k, v projections
    dim3 gproj(DIMC / 128, MTOT / 128);
    k_gemm<<<gproj, 256>>>(h, wq, bq, q, DIMC, DIMC, 0, nullptr, nullptr, 0);
    k_gemm<<<gproj, 256>>>(h, wk, bk, k, DIMC, DIMC, 0, nullptr, nullptr, 0);
    k_gemm<<<gproj, 256>>>(h, wa, ba, v, DIMC, DIMC, 0, nullptr, nullptr, 0);

    // 3. L2 normalize q,k + diag terms
    k_norm<<<MTOT / 8, 256>>>(q, k, dq, dk);

    // 4. FAVOR+ feature maps  qp/kp = ratio*(exp(qn@proj^T - diag) + eps)
    k_gemm<<<gproj, 256>>>(q, proj, nullptr, qp, DIMC, DIMC, 3, dq, nullptr, 0);
    k_gemm<<<gproj, 256>>>(k, proj, nullptr, kp, DIMC, DIMC, 3, dk, nullptr, 0);

    // 5. k_sum and ctx^T (zero then accumulate)
    k_zero<<<(BAT * DIMC * DIMC + 255) / 256, 256>>>(ctx, BAT * DIMC * DIMC);
    k_zero<<<(BAT * DIMC + 255) / 256, 256>>>(ksum, BAT * DIMC);
    k_colsum<<<dim3(32, BAT), 256>>>(kp, ksum);
    k_atb<<<dim3(DIMC / 64, DIMC / 64, BAT * 8), 256>>>(v, kp, ctx);

    // 6. D_inv per token
    k_dinv<<<MTOT / 8, 256>>>(qp, ksum, di);

    // 7. out = D_inv * (qp @ ctx^T^T), fused residual add -> t (in place, safe)
    k_gemm<<<gproj, 256>>>(qp, ctx, nullptr, t, DIMC, DIMC, 4, di, t, DIMC * DIMC);

    // 8. LN2 + MLP (gelu fused, residual fused) -> t
    k_ln<<<MTOT / 8, 256>>>(t, g2, b2, h);
    k_gemm<<<dim3(HID / 128, MTOT / 128), 256>>>(h, w1, fb1, m, DIMC, HID, 1,
                                                 nullptr, nullptr, 0);
    k_gemm<<<dim3(DIMC / 128, MTOT / 128), 256>>>(m, w2, fb2, t, HID, DIMC, 2,
                                                  nullptr, t, 0);

    // 9. transpose back to [B,C,H,W]
    k_out_tr<<<dim3(TOK / 32, DIMC / 32, BAT), 256>>>(t, out);
}

// round 4
// speedup vs baseline: 1.2746x; 1.2746x over previous
#include <cuda_runtime.h>
#include <math.h>

// ---------------------------------------------------------------------------
// ENL transformer block (Performer / FAVOR+ linear attention), fp32 + FFMA2.
// B=8, C=256, H=W=64 -> N=4096 tokens/batch, F=256 features, MLP hidden=1024.
// ---------------------------------------------------------------------------

#define TOK   4096
#define BAT   8
#define DIMC  256
#define HID   1024
#define MTOT  (BAT * TOK)          // 32768 rows total

typedef unsigned long long ull;

// ------------------------------ scratch ------------------------------------
__device__ float g_t  [(size_t)BAT * TOK * DIMC];   // tokens / residual stream
__device__ float g_h  [(size_t)BAT * TOK * DIMC];   // layernorm output (reused)
__device__ float g_q  [(size_t)BAT * TOK * DIMC];
__device__ float g_k  [(size_t)BAT * TOK * DIMC];
__device__ float g_v  [(size_t)BAT * TOK * DIMC];
__device__ float g_qp [(size_t)BAT * TOK * DIMC];
__device__ float g_kp [(size_t)BAT * TOK * DIMC];
__device__ float g_m  [(size_t)BAT * TOK * HID];    // MLP hidden
__device__ float g_ctx[(size_t)BAT * DIMC * DIMC];  // ctx^T  [b][c][f]
__device__ float g_ksum[BAT * DIMC];
__device__ float g_dq [(size_t)BAT * TOK];          // 0.5*||qn||^2
__device__ float g_dk [(size_t)BAT * TOK];
__device__ float g_di [(size_t)BAT * TOK];          // D_inv

// ---------------------------- packed fp32x2 --------------------------------
__device__ __forceinline__ void ffma2(ull& d, ull a, ull b) {
    asm("fma.rn.f32x2 %0, %1, %2, %0;" : "+l"(d) : "l"(a), "l"(b));
}
__device__ __forceinline__ ull pack2(float x) {
    ull r;
    asm("mov.b64 %0, {%1, %1};" : "=l"(r) : "f"(x));
    return r;
}
union U2 { ull u; float2 f; };

// ---------------------------------------------------------------------------
// K1: transpose [B,C,N] -> [B,N,C], store shortcut t and LayerNorm1 output h.
// ---------------------------------------------------------------------------
__global__ void __launch_bounds__(256) k_tr_ln(
    const float* __restrict__ x, const float* __restrict__ g,
    const float* __restrict__ bta, float* __restrict__ t, float* __restrict__ h)
{
    __shared__ float tile[32][257];
    int b  = blockIdx.y;
    int n0 = blockIdx.x * 32;
    const float* xb = x + (size_t)b * DIMC * TOK;
    int tx = threadIdx.x & 31, ty = threadIdx.x >> 5;   // ty 0..7
    #pragma unroll 4
    for (int cc = 0; cc < 32; cc++) {
        int c = cc * 8 + ty;
        tile[tx][c] = xb[(size_t)c * TOK + n0 + tx];
    }
    __syncthreads();
    for (int rep = 0; rep < 4; rep++) {
        int nl = ty + rep * 8;
        float v[8], s = 0.f, sq = 0.f;
        #pragma unroll
        for (int i = 0; i < 8; i++) {
            v[i] = tile[nl][tx + 32 * i];
            s += v[i]; sq += v[i] * v[i];
        }
        #pragma unroll
        for (int o = 16; o; o >>= 1) {
            s  += __shfl_xor_sync(~0u, s,  o);
            sq += __shfl_xor_sync(~0u, sq, o);
        }
        float mu  = s * (1.f / DIMC);
        float var = sq * (1.f / DIMC) - mu * mu;
        float inv = rsqrtf(var + 1e-5f);
        size_t base = ((size_t)b * TOK + n0 + nl) * DIMC;
        #pragma unroll
        for (int i = 0; i < 8; i++) {
            int c = tx + 32 * i;
            t[base + c] = v[i];
            h[base + c] = (v[i] - mu) * inv * g[c] + bta[c];
        }
    }
}

// ---------------------------------------------------------------------------
// LayerNorm2 (no transpose): warp per token.
// ---------------------------------------------------------------------------
__global__ void __launch_bounds__(256) k_ln(
    const float* __restrict__ t, const float* __restrict__ g,
    const float* __restrict__ bta, float* __restrict__ h)
{
    int tok  = blockIdx.x * 8 + (threadIdx.x >> 5);
    int lane = threadIdx.x & 31;
    const float* row = t + (size_t)tok * DIMC;
    float v[8], s = 0.f, sq = 0.f;
    #pragma unroll
    for (int i = 0; i < 8; i++) {
        v[i] = row[lane + 32 * i];
        s += v[i]; sq += v[i] * v[i];
    }
    #pragma unroll
    for (int o = 16; o; o >>= 1) {
        s  += __shfl_xor_sync(~0u, s,  o);
        sq += __shfl_xor_sync(~0u, sq, o);
    }
    float mu  = s * (1.f / DIMC);
    float var = sq * (1.f / DIMC) - mu * mu;
    float inv = rsqrtf(var + 1e-5f);
    float* hr = h + (size_t)tok * DIMC;
    #pragma unroll
    for (int i = 0; i < 8; i++) {
        int c = lane + 32 * i;
        hr[c] = (v[i] - mu) * inv * g[c] + bta[c];
    }
}

// ---------------------------------------------------------------------------
// L2-normalize q,k rows in place (eps=5e-5) + store diag = 0.5*||qn||^2.
// ---------------------------------------------------------------------------
__global__ void __launch_bounds__(256) k_norm(
    float* __restrict__ q, float* __restrict__ k,
    float* __restrict__ dq, float* __restrict__ dk)
{
    int tok  = blockIdx.x * 8 + (threadIdx.x >> 5);
    int lane = threadIdx.x & 31;
    for (int s2 = 0; s2 < 2; s2++) {
        float* row = (s2 == 0 ? q : k) + (size_t)tok * DIMC;
        float v[8], sq = 0.f;
        #pragma unroll
        for (int i = 0; i < 8; i++) {
            v[i] = row[lane + 32 * i];
            sq += v[i] * v[i];
        }
        #pragma unroll
        for (int o = 16; o; o >>= 1) sq += __shfl_xor_sync(~0u, sq, o);
        float nrm = sqrtf(sq);
        float sc  = 1.0f / fmaxf(nrm, 5e-5f);
        #pragma unroll
        for (int i = 0; i < 8; i++) row[lane + 32 * i] = v[i] * sc;
        if (lane == 0) (s2 == 0 ? dq : dk)[tok] = 0.5f * sq * sc * sc;
    }
}

// ---------------------------------------------------------------------------
// Fused GEMM: C[M,N] = epilogue( A[M,K] @ W[N,K]^T + bias ).
// 128x128 tile, BK=16, 256 threads, 8x8 microtile, packed f32x2 FMA,
// double-buffered smem with register-staged global prefetch (1 sync/iter).
// modes: 0 bias | 1 bias+gelu | 2 bias+res | 3 FAVOR+ featuremap | 4 res+dinv*acc
// wbatch>0: per-batch W (W += (m0/TOK)*wbatch) — used for the out GEMM vs ctx.
// ---------------------------------------------------------------------------
__global__ void __launch_bounds__(256, 2) k_gemm(
    const float* __restrict__ A, const float* __restrict__ W,
    const float* __restrict__ bias, float* __restrict__ Cout,
    int K, int N, int mode,
    const float* __restrict__ aux, const float* __restrict__ res,
    int wbatch)
{
    __shared__ __align__(16) float As[2][16][132];
    __shared__ __align__(16) float Ws[2][16][132];
    int m0 = blockIdx.y * 128;
    int n0 = blockIdx.x * 128;
    const float* Wp = W + (wbatch ? (size_t)(m0 / TOK) * wbatch : 0);
    int tid = threadIdx.x;
    int lr = tid >> 2;                 // load row 0..63
    int lk = tid & 3;                  // float4 index along K (BK=16)
    int tx = tid & 15, ty = tid >> 4;  // compute mapping (16 x 16)

    ull acc[8][4];
    #pragma unroll
    for (int i = 0; i < 8; i++)
        #pragma unroll
        for (int j = 0; j < 4; j++) acc[i][j] = 0ull;

    const int nt = K >> 4;
    float4 ra0, ra1, rw0, rw1;

    // prologue: tile 0
    {
        ra0 = *(const float4*)&A [(size_t)(m0 + lr)      * K + lk * 4];
        ra1 = *(const float4*)&A [(size_t)(m0 + 64 + lr) * K + lk * 4];
        rw0 = *(const float4*)&Wp[(size_t)(n0 + lr)      * K + lk * 4];
        rw1 = *(const float4*)&Wp[(size_t)(n0 + 64 + lr) * K + lk * 4];
        As[0][lk*4+0][lr] = ra0.x; As[0][lk*4+1][lr] = ra0.y;
        As[0][lk*4+2][lr] = ra0.z; As[0][lk*4+3][lr] = ra0.w;
        As[0][lk*4+0][64+lr] = ra1.x; As[0][lk*4+1][64+lr] = ra1.y;
        As[0][lk*4+2][64+lr] = ra1.z; As[0][lk*4+3][64+lr] = ra1.w;
        Ws[0][lk*4+0][lr] = rw0.x; Ws[0][lk*4+1][lr] = rw0.y;
        Ws[0][lk*4+2][lr] = rw0.z; Ws[0][lk*4+3][lr] = rw0.w;
        Ws[0][lk*4+0][64+lr] = rw1.x; Ws[0][lk*4+1][64+lr] = rw1.y;
        Ws[0][lk*4+2][64+lr] = rw1.z; Ws[0][lk*4+3][64+lr] = rw1.w;
    }
    __syncthreads();

    for (int kt = 0; kt < nt; kt++) {
        int buf = kt & 1;
        if (kt + 1 < nt) {
            int k0 = (kt + 1) * 16;
            ra0 = *(const float4*)&A [(size_t)(m0 + lr)      * K + k0 + lk * 4];
            ra1 = *(const float4*)&A [(size_t)(m0 + 64 + lr) * K + k0 + lk * 4];
            rw0 = *(const float4*)&Wp[(size_t)(n0 + lr)      * K + k0 + lk * 4];
            rw1 = *(const float4*)&Wp[(size_t)(n0 + 64 + lr) * K + k0 + lk * 4];
        }
        #pragma unroll
        for (int kk = 0; kk < 16; kk++) {
            float4 av0 = *(const float4*)&As[buf][kk][ty * 4];
            float4 av1 = *(const float4*)&As[buf][kk][64 + ty * 4];
            ulonglong2 bq0 = *(const ulonglong2*)&Ws[buf][kk][tx * 4];
            ulonglong2 bq1 = *(const ulonglong2*)&Ws[buf][kk][64 + tx * 4];
            float a[8] = {av0.x, av0.y, av0.z, av0.w, av1.x, av1.y, av1.z, av1.w};
            ull B2[4]  = {bq0.x, bq0.y, bq1.x, bq1.y};
            #pragma unroll
            for (int i = 0; i < 8; i++) {
                ull ai = pack2(a[i]);
                #pragma unroll
                for (int j = 0; j < 4; j++) ffma2(acc[i][j], ai, B2[j]);
            }
        }
        if (kt + 1 < nt) {
            int nb = (kt + 1) & 1;
            As[nb][lk*4+0][lr] = ra0.x; As[nb][lk*4+1][lr] = ra0.y;
            As[nb][lk*4+2][lr] = ra0.z; As[nb][lk*4+3][lr] = ra0.w;
            As[nb][lk*4+0][64+lr] = ra1.x; As[nb][lk*4+1][64+lr] = ra1.y;
            As[nb][lk*4+2][64+lr] = ra1.z; As[nb][lk*4+3][64+lr] = ra1.w;
            Ws[nb][lk*4+0][lr] = rw0.x; Ws[nb][lk*4+1][lr] = rw0.y;
            Ws[nb][lk*4+2][lr] = rw0.z; Ws[nb][lk*4+3][lr] = rw0.w;
            Ws[nb][lk*4+0][64+lr] = rw1.x; Ws[nb][lk*4+1][64+lr] = rw1.y;
            Ws[nb][lk*4+2][64+lr] = rw1.z; Ws[nb][lk*4+3][64+lr] = rw1.w;
        }
        __syncthreads();
    }

    // epilogue: acc[i][j] holds n-pair; i -> row frag, j -> col pair
    #pragma unroll
    for (int i = 0; i < 8; i++) {
        int m = m0 + ((i < 4) ? (ty * 4 + i) : (64 + ty * 4 + i - 4));
        #pragma unroll
        for (int j = 0; j < 4; j++) {
            int n = n0 + ((j < 2) ? (tx * 4 + 2 * j) : (64 + tx * 4 + 2 * (j - 2)));
            U2 u; u.u = acc[i][j];
            float v0 = u.f.x, v1 = u.f.y;
            if (mode == 0)      { v0 += bias[n]; v1 += bias[n + 1]; }
            else if (mode == 1) { v0 += bias[n]; v1 += bias[n + 1];
                                  v0 = v0 * normcdff(v0); v1 = v1 * normcdff(v1); }
            else if (mode == 2) { v0 += bias[n] + res[(size_t)m * N + n];
                                  v1 += bias[n + 1] + res[(size_t)m * N + n + 1]; }
            else if (mode == 3) { float d = aux[m];
                                  v0 = 0.0625f * (expf(v0 - d) + 1e-4f);
                                  v1 = 0.0625f * (expf(v1 - d) + 1e-4f); }
            else                { float d = aux[m];
                                  v0 = res[(size_t)m * N + n]     + d * v0;
                                  v1 = res[(size_t)m * N + n + 1] + d * v1; }
            Cout[(size_t)m * N + n]     = v0;
            Cout[(size_t)m * N + n + 1] = v1;
        }
    }
}

// ---------------------------------------------------------------------------
// ctx^T[b][c][f] += sum_n v[b][n][c] * kp[b][n][f]   (A^T B, K=4096, ksplit=8)
// 64x64 tiles, 32-deep K chunks, packed FMA, fp32 atomic accumulate.
// ---------------------------------------------------------------------------
__global__ void __launch_bounds__(256) k_atb(
    const float* __restrict__ V, const float* __restrict__ KP,
    float* __restrict__ CT)
{
    __shared__ __align__(16) float Vs[32][68];
    __shared__ __align__(16) float Ks[32][68];
    int b  = blockIdx.z >> 3;
    int ks = blockIdx.z & 7;
    int c0 = blockIdx.y * 64;
    int f0 = blockIdx.x * 64;
    const float* Vp = V  + (size_t)b * TOK * DIMC;
    const float* Kp = KP + (size_t)b * TOK * DIMC;
    int tid = threadIdx.x;
    int fc = tid & 15, r0 = tid >> 4;
    int tx = tid & 15, ty = tid >> 4;
    ull acc[4][2];
    #pragma unroll
    for (int i = 0; i < 4; i++) { acc[i][0] = 0ull; acc[i][1] = 0ull; }

    int nbeg = ks * (TOK / 8);
    for (int nt = 0; nt < TOK / 8; nt += 32) {
        #pragma unroll
        for (int rr = 0; rr < 32; rr += 16) {
            int n = nbeg + nt + r0 + rr;
            float4 a = *(const float4*)&Vp[(size_t)n * DIMC + c0 + fc * 4];
            float4 c = *(const float4*)&Kp[(size_t)n * DIMC + f0 + fc * 4];
            *(float4*)&Vs[r0 + rr][fc * 4] = a;
            *(float4*)&Ks[r0 + rr][fc * 4] = c;
        }
        __syncthreads();
        #pragma unroll
        for (int kk = 0; kk < 32; kk++) {
            float4 av = *(const float4*)&Vs[kk][ty * 4];
            ulonglong2 bq = *(const ulonglong2*)&Ks[kk][tx * 4];
            float a[4] = {av.x, av.y, av.z, av.w};
            #pragma unroll
            for (int i = 0; i < 4; i++) {
                ull ai = pack2(a[i]);
                ffma2(acc[i][0], ai, bq.x);
                ffma2(acc[i][1], ai, bq.y);
            }
        }
        __syncthreads();
    }
    float* Cb = CT + (size_t)b * DIMC * DIMC;
    #pragma unroll
    for (int i = 0; i < 4; i++) {
        #pragma unroll
        for (int j = 0; j < 2; j++) {
            U2 u; u.u = acc[i][j];
            atomicAdd(&Cb[(size_t)(c0 + ty * 4 + i) * DIMC + f0 + tx * 4 + 2 * j],     u.f.x);
            atomicAdd(&Cb[(size_t)(c0 + ty * 4 + i) * DIMC + f0 + tx * 4 + 2 * j + 1], u.f.y);
        }
    }
}

// ---------------------------------------------------------------------------
// small helpers
// ---------------------------------------------------------------------------
__global__ void k_zero(float* __restrict__ p, int n)
{
    int i = blockIdx.x * 256 + threadIdx.x;
    if (i < n) p[i] = 0.f;
}

__global__ void __launch_bounds__(256) k_colsum(
    const float* __restrict__ kp, float* __restrict__ ksum)
{
    int b = blockIdx.y, ch = blockIdx.x;
    int f = threadIdx.x;
    const float* base = kp + ((size_t)b * TOK + ch * 128) * DIMC + f;
    float s = 0.f;
    #pragma unroll 8
    for (int i = 0; i < 128; i++) s += base[(size_t)i * DIMC];
    atomicAdd(&ksum[b * DIMC + f], s);
}

__global__ void __launch_bounds__(256) k_dinv(
    const float* __restrict__ qp, const float* __restrict__ ksum,
    float* __restrict__ di)
{
    int tok  = blockIdx.x * 8 + (threadIdx.x >> 5);
    int lane = threadIdx.x & 31;
    int b = tok >> 12;
    const float* row = qp + (size_t)tok * DIMC;
    const float* ks  = ksum + b * DIMC;
    float s = 0.f;
    #pragma unroll
    for (int i = 0; i < 8; i++) { int c = lane + 32 * i; s += row[c] * ks[c]; }
    #pragma unroll
    for (int o = 16; o; o >>= 1) s += __shfl_xor_sync(~0u, s, o);
    if (lane == 0) di[tok] = 1.0f / s;
}

// ---------------------------------------------------------------------------
// output transpose: [B,N,C] -> [B,C,H,W] (=[B,C,N])
// ---------------------------------------------------------------------------
__global__ void __launch_bounds__(256) k_out_tr(
    const float* __restrict__ t, float* __restrict__ out)
{
    __shared__ float tile[32][33];
    int b  = blockIdx.z;
    int n0 = blockIdx.x * 32;
    int c0 = blockIdx.y * 32;
    int tx = threadIdx.x & 31, ty = threadIdx.x >> 5;
    #pragma unroll
    for (int i = 0; i < 32; i += 8)
        tile[ty + i][tx] = t[((size_t)b * TOK + n0 + ty + i) * DIMC + c0 + tx];
    __syncthreads();
    #pragma unroll
    for (int i = 0; i < 32; i += 8)
        out[((size_t)b * DIMC + c0 + ty + i) * TOK + n0 + tx] = tile[tx][ty + i];
}

// ---------------------------------------------------------------------------
// host launch
// ---------------------------------------------------------------------------
extern "C" void kernel_launch(void* const* d_in, const int* in_sizes, int n_in,
                              void* d_out, int out_size)
{
    const float* x    = (const float*)d_in[0];
    const float* proj = (const float*)d_in[1];
    const float* wq   = (const float*)d_in[2];
    const float* bq   = (const float*)d_in[3];
    const float* wk   = (const float*)d_in[4];
    const float* bk   = (const float*)d_in[5];
    const float* wa   = (const float*)d_in[6];
    const float* ba   = (const float*)d_in[7];
    const float* g1   = (const float*)d_in[8];
    const float* b1   = (const float*)d_in[9];
    const float* g2   = (const float*)d_in[10];
    const float* b2   = (const float*)d_in[11];
    const float* w1   = (const float*)d_in[12];
    const float* fb1  = (const float*)d_in[13];
    const float* w2   = (const float*)d_in[14];
    const float* fb2  = (const float*)d_in[15];
    float* out = (float*)d_out;
    (void)in_sizes; (void)n_in; (void)out_size;

    float *t, *h, *q, *k, *v, *qp, *kp, *m, *ctx, *ksum, *dq, *dk, *di;
    cudaGetSymbolAddress((void**)&t,    g_t);
    cudaGetSymbolAddress((void**)&h,    g_h);
    cudaGetSymbolAddress((void**)&q,    g_q);
    cudaGetSymbolAddress((void**)&k,    g_k);
    cudaGetSymbolAddress((void**)&v,    g_v);
    cudaGetSymbolAddress((void**)&qp,   g_qp);
    cudaGetSymbolAddress((void**)&kp,   g_kp);
    cudaGetSymbolAddress((void**)&m,    g_m);
    cudaGetSymbolAddress((void**)&ctx,  g_ctx);
    cudaGetSymbolAddress((void**)&ksum, g_ksum);
    cudaGetSymbolAddress((void**)&dq,   g_dq);
    cudaGetSymbolAddress((void**)&dk,   g_dk);
    cudaGetSymbolAddress((void**)&di,   g_di);

    // 1. transpose + LN1 (t = shortcut, h = normed)
    k_tr_ln<<<dim3(TOK / 32, BAT), 256>>>(x, g1, b1, t, h);

    // 2. q, k, v projections
    dim3 gproj(DIMC / 128, MTOT / 128);
    k_gemm<<<gproj, 256>>>(h, wq, bq, q, DIMC, DIMC, 0, nullptr, nullptr, 0);
    k_gemm<<<gproj, 256>>>(h, wk, bk, k, DIMC, DIMC, 0, nullptr, nullptr, 0);
    k_gemm<<<gproj, 256>>>(h, wa, ba, v, DIMC, DIMC, 0, nullptr, nullptr, 0);

    // 3. L2 normalize q,k + diag terms
    k_norm<<<MTOT / 8, 256>>>(q, k, dq, dk);

    // 4. FAVOR+ feature maps  qp/kp = ratio*(exp(qn@proj^T - diag) + eps)
    k_gemm<<<gproj, 256>>>(q, proj, nullptr, qp, DIMC, DIMC, 3, dq, nullptr, 0);
    k_gemm<<<gproj, 256>>>(k, proj, nullptr, kp, DIMC, DIMC, 3, dk, nullptr, 0);

    // 5. k_sum and ctx^T (zero then accumulate)
    k_zero<<<(BAT * DIMC * DIMC + 255) / 256, 256>>>(ctx, BAT * DIMC * DIMC);
    k_zero<<<(BAT * DIMC + 255) / 256, 256>>>(ksum, BAT * DIMC);
    k_colsum<<<dim3(32, BAT), 256>>>(kp, ksum);
    k_atb<<<dim3(DIMC / 64, DIMC / 64, BAT * 8), 256>>>(v, kp, ctx);

    // 6. D_inv per token
    k_dinv<<<MTOT / 8, 256>>>(qp, ksum, di);

    // 7. out = D_inv * (qp @ ctx^T^T), fused residual add -> t (in place, safe)
    k_gemm<<<gproj, 256>>>(qp, ctx, nullptr, t, DIMC, DIMC, 4, di, t, DIMC * DIMC);

    // 8. LN2 + MLP (gelu fused, residual fused) -> t
    k_ln<<<MTOT / 8, 256>>>(t, g2, b2, h);
    k_gemm<<<dim3(HID / 128, MTOT / 128), 256>>>(h, w1, fb1, m, DIMC, HID, 1,
                                                 nullptr, nullptr, 0);
    k_gemm<<<dim3(DIMC / 128, MTOT / 128), 256>>>(m, w2, fb2, t, HID, DIMC, 2,
                                                  nullptr, t, 0);

    // 9. transpose back to [B,C,H,W]
    k_out_tr<<<dim3(TOK / 32, DIMC / 32, BAT), 256>>>(t, out);
}

// round 9
// speedup vs baseline: 2.4317x; 1.9078x over previous
#include <cuda_runtime.h>
#include <cuda_bf16.h>
#include <math.h>
#include <stdint.h>

// ---------------------------------------------------------------------------
// ENL transformer block (Performer / FAVOR+), mma.sync bf16-split GEMMs.
// B=8, C=256, N=4096 tokens/batch, F=256, MLP hidden=1024.
// ---------------------------------------------------------------------------

#define TOK   4096
#define BAT   8
#define DIMC  256
#define HID   1024
#define MTOT  (BAT * TOK)

typedef unsigned long long ull;

// ------------------------------ scratch ------------------------------------
__device__ float g_t  [(size_t)BAT * TOK * DIMC];
__device__ float g_h  [(size_t)BAT * TOK * DIMC];
__device__ float g_q  [(size_t)BAT * TOK * DIMC];
__device__ float g_k  [(size_t)BAT * TOK * DIMC];
__device__ float g_v  [(size_t)BAT * TOK * DIMC];
__device__ float g_qp [(size_t)BAT * TOK * DIMC];
__device__ float g_kp [(size_t)BAT * TOK * DIMC];
__device__ float g_m  [(size_t)BAT * TOK * HID];
__device__ float g_ctx[(size_t)BAT * DIMC * DIMC];
__device__ float g_ksum[BAT * DIMC];
__device__ float g_dq [(size_t)BAT * TOK];
__device__ float g_dk [(size_t)BAT * TOK];
__device__ float g_di [(size_t)BAT * TOK];

// ---------------------------- packed fp32x2 (k_atb) ------------------------
__device__ __forceinline__ void ffma2(ull& d, ull a, ull b) {
    asm("fma.rn.f32x2 %0, %1, %2, %0;" : "+l"(d) : "l"(a), "l"(b));
}
__device__ __forceinline__ ull pack2f(float x) {
    ull r; asm("mov.b64 %0, {%1, %1};" : "=l"(r) : "f"(x)); return r;
}
union U2 { ull u; float2 f; };

// ---------------------------- bf16 helpers ---------------------------------
__device__ __forceinline__ uint32_t bf2pack(float lo, float hi) {
    uint32_t r;
    asm("cvt.rn.bf16x2.f32 %0, %1, %2;" : "=r"(r) : "f"(hi), "f"(lo));
    return r;
}

// mma.sync m16n8k16 row.col f32 += bf16*bf16
__device__ __forceinline__ void mma16816(float* c, const uint32_t* a,
                                         const uint32_t* b) {
    asm volatile(
        "mma.sync.aligned.m16n8k16.row.col.f32.bf16.bf16.f32 "
        "{%0,%1,%2,%3}, {%4,%5,%6,%7}, {%8,%9}, {%0,%1,%2,%3};"
        : "+f"(c[0]), "+f"(c[1]), "+f"(c[2]), "+f"(c[3])
        : "r"(a[0]), "r"(a[1]), "r"(a[2]), "r"(a[3]), "r"(b[0]), "r"(b[1]));
}

// ---------------------------------------------------------------------------
// mma.sync GEMM: C[M,N] = epi( A[M,K] @ W[N,K]^T ), bf16 hi/lo 3-pass split.
// CTA 128x128, BK=16, 8 warps (warp tile 64x32), double-buffered smem,
// register-staged prefetch, 1 sync per K-chunk.
// modes: 0 bias | 1 bias+gelu | 2 bias+res | 3 featuremap | 4 res+aux*acc
// ---------------------------------------------------------------------------
#define BKP 24   // padded smem row stride (bf16): (r*12 mod 32) is a permutation

__device__ __forceinline__ void split_store(__nv_bfloat16* hi, __nv_bfloat16* lo,
                                            int off, float4 v) {
    __nv_bfloat16 h0 = __float2bfloat16(v.x);
    __nv_bfloat16 h1 = __float2bfloat16(v.y);
    __nv_bfloat16 h2 = __float2bfloat16(v.z);
    __nv_bfloat16 h3 = __float2bfloat16(v.w);
    float l0 = v.x - __bfloat162float(h0);
    float l1 = v.y - __bfloat162float(h1);
    float l2 = v.z - __bfloat162float(h2);
    float l3 = v.w - __bfloat162float(h3);
    uint32_t hp0 = ((uint32_t)__bfloat16_as_ushort(h1) << 16) | __bfloat16_as_ushort(h0);
    uint32_t hp1 = ((uint32_t)__bfloat16_as_ushort(h3) << 16) | __bfloat16_as_ushort(h2);
    *(uint2*)(hi + off) = make_uint2(hp0, hp1);
    *(uint2*)(lo + off) = make_uint2(bf2pack(l0, l1), bf2pack(l2, l3));
}

__device__ __forceinline__ void ld_afrag(uint32_t af[4][4],
                                         const __nv_bfloat16* S, int ar, int ac) {
    #pragma unroll
    for (int mt = 0; mt < 4; mt++) {
        const __nv_bfloat16* p = S + (ar + mt * 16) * BKP + ac;
        af[mt][0] = *(const uint32_t*)(p);
        af[mt][1] = *(const uint32_t*)(p + 8 * BKP);
        af[mt][2] = *(const uint32_t*)(p + 8);
        af[mt][3] = *(const uint32_t*)(p + 8 * BKP + 8);
    }
}
__device__ __forceinline__ void ld_bfrag(uint32_t bf[4][2],
                                         const __nv_bfloat16* S, int br, int ac) {
    #pragma unroll
    for (int nt = 0; nt < 4; nt++) {
        const __nv_bfloat16* p = S + (br + nt * 8) * BKP + ac;
        bf[nt][0] = *(const uint32_t*)(p);
        bf[nt][1] = *(const uint32_t*)(p + 8);
    }
}
__device__ __forceinline__ void mma_all(float acc[16][4],
                                        uint32_t af[4][4], uint32_t bf[4][2]) {
    #pragma unroll
    for (int mt = 0; mt < 4; mt++)
        #pragma unroll
        for (int nt = 0; nt < 4; nt++)
            mma16816(acc[mt * 4 + nt], af[mt], bf[nt]);
}

__global__ void __launch_bounds__(256, 2) k_gemm_mma(
    const float* __restrict__ A, const float* __restrict__ W,
    const float* __restrict__ bias, float* __restrict__ Cout,
    int K, int N, int mode,
    const float* __restrict__ aux, const float* __restrict__ res,
    int wbatch)
{
    __shared__ __nv_bfloat16 sAh[2][128 * BKP], sAl[2][128 * BKP];
    __shared__ __nv_bfloat16 sWh[2][128 * BKP], sWl[2][128 * BKP];

    int tid = threadIdx.x;
    int lane = tid & 31, wid = tid >> 5;
    int wm = wid & 1, wn = wid >> 1;            // warp tile (wm*64, wn*32)
    int m0 = blockIdx.y * 128, n0 = blockIdx.x * 128;
    const float* Wp = W + (wbatch ? (size_t)(m0 / TOK) * (size_t)wbatch : 0);

    float acc[16][4];
    #pragma unroll
    for (int i = 0; i < 16; i++)
        #pragma unroll
        for (int j = 0; j < 4; j++) acc[i][j] = 0.f;

    int row0 = tid >> 2;        // 0..63 (also +64)
    int kg   = tid & 3;         // float4 index within BK=16
    int soff0 = row0 * BKP + kg * 4;
    int soff1 = (row0 + 64) * BKP + kg * 4;

    int ar = wm * 64 + (lane >> 2);
    int br = wn * 32 + (lane >> 2);
    int ac = (lane & 3) * 2;

    const int nc = K >> 4;
    float4 a0, a1, w0, w1;

    // prologue: chunk 0
    a0 = *(const float4*)&A [(size_t)(m0 + row0)      * K + kg * 4];
    a1 = *(const float4*)&A [(size_t)(m0 + row0 + 64) * K + kg * 4];
    w0 = *(const float4*)&Wp[(size_t)(n0 + row0)      * K + kg * 4];
    w1 = *(const float4*)&Wp[(size_t)(n0 + row0 + 64) * K + kg * 4];
    split_store(sAh[0], sAl[0], soff0, a0);
    split_store(sAh[0], sAl[0], soff1, a1);
    split_store(sWh[0], sWl[0], soff0, w0);
    split_store(sWh[0], sWl[0], soff1, w1);
    __syncthreads();

    for (int c = 0; c < nc; c++) {
        int buf = c & 1;
        if (c + 1 < nc) {
            int kc = (c + 1) << 4;
            a0 = *(const float4*)&A [(size_t)(m0 + row0)      * K + kc + kg * 4];
            a1 = *(const float4*)&A [(size_t)(m0 + row0 + 64) * K + kc + kg * 4];
            w0 = *(const float4*)&Wp[(size_t)(n0 + row0)      * K + kc + kg * 4];
            w1 = *(const float4*)&Wp[(size_t)(n0 + row0 + 64) * K + kc + kg * 4];
        }
        {
            uint32_t af[4][4], bf[4][2];
            ld_afrag(af, sAh[buf], ar, ac);      // A-hi
            ld_bfrag(bf, sWh[buf], br, ac);      // * W-hi
            mma_all(acc, af, bf);
            ld_bfrag(bf, sWl[buf], br, ac);      // * W-lo (reuse A-hi frags)
            mma_all(acc, af, bf);
            ld_afrag(af, sAl[buf], ar, ac);      // A-lo
            ld_bfrag(bf, sWh[buf], br, ac);      // * W-hi
            mma_all(acc, af, bf);
        }
        if (c + 1 < nc) {
            int nb = (c + 1) & 1;
            split_store(sAh[nb], sAl[nb], soff0, a0);
            split_store(sAh[nb], sAl[nb], soff1, a1);
            split_store(sWh[nb], sWl[nb], soff0, w0);
            split_store(sWh[nb], sWl[nb], soff1, w1);
        }
        __syncthreads();
    }

    // epilogue
    #pragma unroll
    for (int mt = 0; mt < 4; mt++) {
        #pragma unroll
        for (int half = 0; half < 2; half++) {
            int m = m0 + wm * 64 + mt * 16 + (lane >> 2) + half * 8;
            float am = (mode >= 3) ? aux[m] : 0.f;
            #pragma unroll
            for (int nt = 0; nt < 4; nt++) {
                int n = n0 + wn * 32 + nt * 8 + (lane & 3) * 2;
                float v0 = acc[mt * 4 + nt][half * 2 + 0];
                float v1 = acc[mt * 4 + nt][half * 2 + 1];
                if (mode == 0)      { v0 += bias[n]; v1 += bias[n + 1]; }
                else if (mode == 1) { v0 += bias[n]; v1 += bias[n + 1];
                                      v0 *= normcdff(v0); v1 *= normcdff(v1); }
                else if (mode == 2) { v0 += bias[n]     + res[(size_t)m * N + n];
                                      v1 += bias[n + 1] + res[(size_t)m * N + n + 1]; }
                else if (mode == 3) { v0 = 0.0625f * (expf(v0 - am) + 1e-4f);
                                      v1 = 0.0625f * (expf(v1 - am) + 1e-4f); }
                else                { v0 = res[(size_t)m * N + n]     + am * v0;
                                      v1 = res[(size_t)m * N + n + 1] + am * v1; }
                *(float2*)&Cout[(size_t)m * N + n] = make_float2(v0, v1);
            }
        }
    }
}

// ---------------------------------------------------------------------------
// K1: transpose [B,C,N] -> [B,N,C] + LayerNorm1 (t = shortcut, h = normed)
// ---------------------------------------------------------------------------
__global__ void __launch_bounds__(256) k_tr_ln(
    const float* __restrict__ x, const float* __restrict__ g,
    const float* __restrict__ bta, float* __restrict__ t, float* __restrict__ h)
{
    __shared__ float tile[32][257];
    int b  = blockIdx.y;
    int n0 = blockIdx.x * 32;
    const float* xb = x + (size_t)b * DIMC * TOK;
    int tx = threadIdx.x & 31, ty = threadIdx.x >> 5;
    #pragma unroll 4
    for (int cc = 0; cc < 32; cc++) {
        int c = cc * 8 + ty;
        tile[tx][c] = xb[(size_t)c * TOK + n0 + tx];
    }
    __syncthreads();
    for (int rep = 0; rep < 4; rep++) {
        int nl = ty + rep * 8;
        float v[8], s = 0.f, sq = 0.f;
        #pragma unroll
        for (int i = 0; i < 8; i++) {
            v[i] = tile[nl][tx + 32 * i];
            s += v[i]; sq += v[i] * v[i];
        }
        #pragma unroll
        for (int o = 16; o; o >>= 1) {
            s  += __shfl_xor_sync(~0u, s,  o);
            sq += __shfl_xor_sync(~0u, sq, o);
        }
        float mu  = s * (1.f / DIMC);
        float var = sq * (1.f / DIMC) - mu * mu;
        float inv = rsqrtf(var + 1e-5f);
        size_t base = ((size_t)b * TOK + n0 + nl) * DIMC;
        #pragma unroll
        for (int i = 0; i < 8; i++) {
            int c = tx + 32 * i;
            t[base + c] = v[i];
            h[base + c] = (v[i] - mu) * inv * g[c] + bta[c];
        }
    }
}

// ---------------------------------------------------------------------------
// LayerNorm2: warp per token.
// ---------------------------------------------------------------------------
__global__ void __launch_bounds__(256) k_ln(
    const float* __restrict__ t, const float* __restrict__ g,
    const float* __restrict__ bta, float* __restrict__ h)
{
    int tok  = blockIdx.x * 8 + (threadIdx.x >> 5);
    int lane = threadIdx.x & 31;
    const float* row = t + (size_t)tok * DIMC;
    float v[8], s = 0.f, sq = 0.f;
    #pragma unroll
    for (int i = 0; i < 8; i++) {
        v[i] = row[lane + 32 * i];
        s += v[i]; sq += v[i] * v[i];
    }
    #pragma unroll
    for (int o = 16; o; o >>= 1) {
        s  += __shfl_xor_sync(~0u, s,  o);
        sq += __shfl_xor_sync(~0u, sq, o);
    }
    float mu  = s * (1.f / DIMC);
    float var = sq * (1.f / DIMC) - mu * mu;
    float inv = rsqrtf(var + 1e-5f);
    float* hr = h + (size_t)tok * DIMC;
    #pragma unroll
    for (int i = 0; i < 8; i++) {
        int c = lane + 32 * i;
        hr[c] = (v[i] - mu) * inv * g[c] + bta[c];
    }
}

// ---------------------------------------------------------------------------
// L2-normalize q,k rows in place + diag = 0.5*||qn||^2.
// ---------------------------------------------------------------------------
__global__ void __launch_bounds__(256) k_norm(
    float* __restrict__ q, float* __restrict__ k,
    float* __restrict__ dq, float* __restrict__ dk)
{
    int tok  = blockIdx.x * 8 + (threadIdx.x >> 5);
    int lane = threadIdx.x & 31;
    for (int s2 = 0; s2 < 2; s2++) {
        float* row = (s2 == 0 ? q : k) + (size_t)tok * DIMC;
        float v[8], sq = 0.f;
        #pragma unroll
        for (int i = 0; i < 8; i++) {
            v[i] = row[lane + 32 * i];
            sq += v[i] * v[i];
        }
        #pragma unroll
        for (int o = 16; o; o >>= 1) sq += __shfl_xor_sync(~0u, sq, o);
        float nrm = sqrtf(sq);
        float sc  = 1.0f / fmaxf(nrm, 5e-5f);
        #pragma unroll
        for (int i = 0; i < 8; i++) row[lane + 32 * i] = v[i] * sc;
        if (lane == 0) (s2 == 0 ? dq : dk)[tok] = 0.5f * sq * sc * sc;
    }
}

// ---------------------------------------------------------------------------
// ctx^T[b][c][f] += sum_n v[b][n][c]*kp[b][n][f]  (fp32 FFMA2, ksplit=8)
// ---------------------------------------------------------------------------
__global__ void __launch_bounds__(256) k_atb(
    const float* __restrict__ V, const float* __restrict__ KP,
    float* __restrict__ CT)
{
    __shared__ __align__(16) float Vs[32][68];
    __shared__ __align__(16) float Ks[32][68];
    int b  = blockIdx.z >> 3;
    int ks = blockIdx.z & 7;
    int c0 = blockIdx.y * 64;
    int f0 = blockIdx.x * 64;
    const float* Vp = V  + (size_t)b * TOK * DIMC;
    const float* Kp = KP + (size_t)b * TOK * DIMC;
    int tid = threadIdx.x;
    int fc = tid & 15, r0 = tid >> 4;
    int tx = tid & 15, ty = tid >> 4;
    ull acc[4][2];
    #pragma unroll
    for (int i = 0; i < 4; i++) { acc[i][0] = 0ull; acc[i][1] = 0ull; }

    int nbeg = ks * (TOK / 8);
    for (int nt = 0; nt < TOK / 8; nt += 32) {
        #pragma unroll
        for (int rr = 0; rr < 32; rr += 16) {
            int n = nbeg + nt + r0 + rr;
            *(float4*)&Vs[r0 + rr][fc * 4] = *(const float4*)&Vp[(size_t)n * DIMC + c0 + fc * 4];
            *(float4*)&Ks[r0 + rr][fc * 4] = *(const float4*)&Kp[(size_t)n * DIMC + f0 + fc * 4];
        }
        __syncthreads();
        #pragma unroll
        for (int kk = 0; kk < 32; kk++) {
            float4 av = *(const float4*)&Vs[kk][ty * 4];
            ulonglong2 bq = *(const ulonglong2*)&Ks[kk][tx * 4];
            float a[4] = {av.x, av.y, av.z, av.w};
            #pragma unroll
            for (int i = 0; i < 4; i++) {
                ull ai = pack2f(a[i]);
                ffma2(acc[i][0], ai, bq.x);
                ffma2(acc[i][1], ai, bq.y);
            }
        }
        __syncthreads();
    }
    float* Cb = CT + (size_t)b * DIMC * DIMC;
    #pragma unroll
    for (int i = 0; i < 4; i++)
        #pragma unroll
        for (int j = 0; j < 2; j++) {
            U2 u; u.u = acc[i][j];
            atomicAdd(&Cb[(size_t)(c0 + ty * 4 + i) * DIMC + f0 + tx * 4 + 2 * j],     u.f.x);
            atomicAdd(&Cb[(size_t)(c0 + ty * 4 + i) * DIMC + f0 + tx * 4 + 2 * j + 1], u.f.y);
        }
}

// ---------------------------------------------------------------------------
// small helpers
// ---------------------------------------------------------------------------
__global__ void k_zero(float* __restrict__ p, int n)
{
    int i = blockIdx.x * 256 + threadIdx.x;
    if (i < n) p[i] = 0.f;
}

__global__ void __launch_bounds__(256) k_colsum(
    const float* __restrict__ kp, float* __restrict__ ksum)
{
    int b = blockIdx.y, ch = blockIdx.x;
    int f = threadIdx.x;
    const float* base = kp + ((size_t)b * TOK + ch * 128) * DIMC + f;
    float s = 0.f;
    #pragma unroll 8
    for (int i = 0; i < 128; i++) s += base[(size_t)i * DIMC];
    atomicAdd(&ksum[b * DIMC + f], s);
}

__global__ void __launch_bounds__(256) k_dinv(
    const float* __restrict__ qp, const float* __restrict__ ksum,
    float* __restrict__ di)
{
    int tok  = blockIdx.x * 8 + (threadIdx.x >> 5);
    int lane = threadIdx.x & 31;
    int b = tok >> 12;
    const float* row = qp + (size_t)tok * DIMC;
    const float* ks  = ksum + b * DIMC;
    float s = 0.f;
    #pragma unroll
    for (int i = 0; i < 8; i++) { int c = lane + 32 * i; s += row[c] * ks[c]; }
    #pragma unroll
    for (int o = 16; o; o >>= 1) s += __shfl_xor_sync(~0u, s, o);
    if (lane == 0) di[tok] = 1.0f / s;
}

__global__ void __launch_bounds__(256) k_out_tr(
    const float* __restrict__ t, float* __restrict__ out)
{
    __shared__ float tile[32][33];
    int b  = blockIdx.z;
    int n0 = blockIdx.x * 32;
    int c0 = blockIdx.y * 32;
    int tx = threadIdx.x & 31, ty = threadIdx.x >> 5;
    #pragma unroll
    for (int i = 0; i < 32; i += 8)
        tile[ty + i][tx] = t[((size_t)b * TOK + n0 + ty + i) * DIMC + c0 + tx];
    __syncthreads();
    #pragma unroll
    for (int i = 0; i < 32; i += 8)
        out[((size_t)b * DIMC + c0 + ty + i) * TOK + n0 + tx] = tile[tx][ty + i];
}

// ---------------------------------------------------------------------------
// host launch
// ---------------------------------------------------------------------------
extern "C" void kernel_launch(void* const* d_in, const int* in_sizes, int n_in,
                              void* d_out, int out_size)
{
    const float* x    = (const float*)d_in[0];
    const float* proj = (const float*)d_in[1];
    const float* wq   = (const float*)d_in[2];
    const float* bq   = (const float*)d_in[3];
    const float* wk   = (const float*)d_in[4];
    const float* bk   = (const float*)d_in[5];
    const float* wa   = (const float*)d_in[6];
    const float* ba   = (const float*)d_in[7];
    const float* g1   = (const float*)d_in[8];
    const float* b1   = (const float*)d_in[9];
    const float* g2   = (const float*)d_in[10];
    const float* b2   = (const float*)d_in[11];
    const float* w1   = (const float*)d_in[12];
    const float* fb1  = (const float*)d_in[13];
    const float* w2   = (const float*)d_in[14];
    const float* fb2  = (const float*)d_in[15];
    float* out = (float*)d_out;
    (void)in_sizes; (void)n_in; (void)out_size;

    float *t, *h, *q, *k, *v, *qp, *kp, *m, *ctx, *ksum, *dq, *dk, *di;
    cudaGetSymbolAddress((void**)&t,    g_t);
    cudaGetSymbolAddress((void**)&h,    g_h);
    cudaGetSymbolAddress((void**)&q,    g_q);
    cudaGetSymbolAddress((void**)&k,    g_k);
    cudaGetSymbolAddress((void**)&v,    g_v);
    cudaGetSymbolAddress((void**)&qp,   g_qp);
    cudaGetSymbolAddress((void**)&kp,   g_kp);
    cudaGetSymbolAddress((void**)&m,    g_m);
    cudaGetSymbolAddress((void**)&ctx,  g_ctx);
    cudaGetSymbolAddress((void**)&ksum, g_ksum);
    cudaGetSymbolAddress((void**)&dq,   g_dq);
    cudaGetSymbolAddress((void**)&dk,   g_dk);
    cudaGetSymbolAddress((void**)&di,   g_di);

    // 1. transpose + LN1
    k_tr_ln<<<dim3(TOK / 32, BAT), 256>>>(x, g1, b1, t, h);

    // 2. q, k, v projections (tensor cores)
    dim3 gproj(DIMC / 128, MTOT / 128);
    k_gemm_mma<<<gproj, 256>>>(h, wq, bq, q, DIMC, DIMC, 0, nullptr, nullptr, 0);
    k_gemm_mma<<<gproj, 256>>>(h, wk, bk, k, DIMC, DIMC, 0, nullptr, nullptr, 0);
    k_gemm_mma<<<gproj, 256>>>(h, wa, ba, v, DIMC, DIMC, 0, nullptr, nullptr, 0);

    // 3. L2 normalize q,k + diag
    k_norm<<<MTOT / 8, 256>>>(q, k, dq, dk);

    // 4. FAVOR+ feature maps
    k_gemm_mma<<<gproj, 256>>>(q, proj, nullptr, qp, DIMC, DIMC, 3, dq, nullptr, 0);
    k_gemm_mma<<<gproj, 256>>>(k, proj, nullptr, kp, DIMC, DIMC, 3, dk, nullptr, 0);

    // 5. k_sum and ctx^T
    k_zero<<<(BAT * DIMC * DIMC + 255) / 256, 256>>>(ctx, BAT * DIMC * DIMC);
    k_zero<<<(BAT * DIMC + 255) / 256, 256>>>(ksum, BAT * DIMC);
    k_colsum<<<dim3(32, BAT), 256>>>(kp, ksum);
    k_atb<<<dim3(DIMC / 64, DIMC / 64, BAT * 8), 256>>>(v, kp, ctx);

    // 6. D_inv
    k_dinv<<<MTOT / 8, 256>>>(qp, ksum, di);

    // 7. out = res + D_inv * (qp @ ctx^T^T)  (per-batch W = ctx)
    k_gemm_mma<<<gproj, 256>>>(qp, ctx, nullptr, t, DIMC, DIMC, 4, di, t, DIMC * DIMC);

    // 8. LN2 + MLP
    k_ln<<<MTOT / 8, 256>>>(t, g2, b2, h);
    k_gemm_mma<<<dim3(HID / 128, MTOT / 128), 256>>>(h, w1, fb1, m, DIMC, HID, 1,
                                                     nullptr, nullptr, 0);
    k_gemm_mma<<<dim3(DIMC / 128, MTOT / 128), 256>>>(m, w2, fb2, t, HID, DIMC, 2,
                                                      nullptr, t, 0);

    // 9. transpose back
    k_out_tr<<<dim3(TOK / 32, DIMC / 32, BAT), 256>>>(t, out);
}